// round 10
// baseline (speedup 1.0000x reference)
#include <cuda_runtime.h>
#include <cuda_bf16.h>

// Fixed by the reference: 2048x2048 fp32.
// Pass1: box 17(v) x 5(h); Pass2: box 5(v) x 17(h).
//   X1  = X  + boxsum1(Y - X )/N1
//   out = X1 + boxsum2(Y - X1)/N2
// zero-padded sums, N = in-bounds window count. Fully fused: X1 never
// touches DRAM — produced in registers as each warp streams down its strip.
#define H_DIM 2048
#define W_DIM 2048

__device__ __forceinline__ float4 z4() { return make_float4(0.f, 0.f, 0.f, 0.f); }
__device__ __forceinline__ float4 ld4(const float* p) { return *(const float4*)p; }
__device__ __forceinline__ float4 add4(float4 a, float4 b) {
    return make_float4(a.x + b.x, a.y + b.y, a.z + b.z, a.w + b.w);
}
__device__ __forceinline__ float4 sub4(float4 a, float4 b) {
    return make_float4(a.x - b.x, a.y - b.y, a.z - b.z, a.w - b.w);
}

// Horizontal box sums across the warp's 128 strip columns (4 per lane).
// Valid on lanes 1..30 (RH=2) / 2..29 (RH=8).
template <int RH>
__device__ __forceinline__ float4 hsum_warp(float4 t) {
    const unsigned M = 0xffffffffu;
    if constexpr (RH == 2) {
        const float Lz = __shfl_up_sync(M, t.z, 1);
        const float Lw = __shfl_up_sync(M, t.w, 1);
        const float Rx = __shfl_down_sync(M, t.x, 1);
        const float Ry = __shfl_down_sync(M, t.y, 1);
        const float sall = t.x + t.y + t.z + t.w;
        float4 hs;
        hs.y = Lw + sall;
        hs.x = hs.y + Lz - t.w;
        hs.z = sall + Rx;
        hs.w = hs.z - t.x + Ry;
        return hs;
    } else {  // RH == 8
        const float S    = t.x + t.y + t.z + t.w;
        const float Sm2  = __shfl_up_sync(M, S, 2);
        const float Sm1  = __shfl_up_sync(M, S, 1);
        const float Sp1  = __shfl_down_sync(M, S, 1);
        const float dxm2 = __shfl_up_sync(M, t.x, 2);
        const float dym2 = __shfl_up_sync(M, t.y, 2);
        const float dzm2 = __shfl_up_sync(M, t.z, 2);
        const float dxp2 = __shfl_down_sync(M, t.x, 2);
        const float dyp2 = __shfl_down_sync(M, t.y, 2);
        const float dzp2 = __shfl_down_sync(M, t.z, 2);
        const float dwp2 = __shfl_down_sync(M, t.w, 2);
        float4 hs;
        hs.x = Sm2 + Sm1 + S + Sp1 + dxp2;
        hs.y = hs.x - dxm2 + dyp2;
        hs.z = hs.y - dym2 + dzp2;
        hs.w = hs.z - dzm2 + dwp2;
        return hs;
    }
}

__global__ __launch_bounds__(256)
void guided_fused(const float* __restrict__ X,
                  const float* __restrict__ Y,
                  float* __restrict__ out)
{
    // Output lanes 3..28: pass1 hsum needs lane+-1, pass2 hsum needs lane+-2
    // on top of valid d2 (lanes 1..30). 26 lanes * 4 cols = 104 output cols.
    constexpr int OUTW = 104, LANELO = 3, LANEHI = 28;
    constexpr int STRIPS = 20;          // 20*104 = 2080 >= 2048
    constexpr int SEG = 16, SEGS = H_DIM / SEG;   // 128

    const int wg    = blockIdx.x * 8 + (threadIdx.x >> 5);
    const int lane  = threadIdx.x & 31;
    const int strip = wg % STRIPS;
    const int segy  = wg / STRIPS;
    if (segy >= SEGS) return;           // uniform per warp (never true here)

    const int r0  = segy * SEG;
    const int gj0 = strip * OUTW - 4 * LANELO + 4 * lane;   // 4-aligned
    const bool colIn = (gj0 >= 0) && (gj0 + 3 < W_DIM);
    const bool c0 = (unsigned)(gj0 + 0) < (unsigned)W_DIM;
    const bool c1 = (unsigned)(gj0 + 1) < (unsigned)W_DIM;
    const bool c2 = (unsigned)(gj0 + 2) < (unsigned)W_DIM;
    const bool c3 = (unsigned)(gj0 + 3) < (unsigned)W_DIM;

    // Predicated row load of one image (zeros outside).
    auto load4p = [&](const float* base, int gi) -> float4 {
        if ((unsigned)gi >= (unsigned)H_DIM) return z4();
        const float* p = base + (size_t)gi * W_DIM + gj0;
        if (colIn) return ld4(p);
        float4 r = z4();
        if (c0) r.x = p[0];
        if (c1) r.y = p[1];
        if (c2) r.z = p[2];
        if (c3) r.w = p[3];
        return r;
    };
    // D1 = Y - X at row gi (zeros outside image).
    auto loadD1 = [&](int gi) -> float4 {
        if ((unsigned)gi >= (unsigned)H_DIM) return z4();
        const float* yp = Y + (size_t)gi * W_DIM + gj0;
        const float* xp = X + (size_t)gi * W_DIM + gj0;
        if (colIn) return sub4(ld4(yp), ld4(xp));
        float4 r = z4();
        if (c0) r.x = yp[0] - xp[0];
        if (c1) r.y = yp[1] - xp[1];
        if (c2) r.z = yp[2] - xp[2];
        if (c3) r.w = yp[3] - xp[3];
        return r;
    };

    // Per-column horizontal reciprocal counts (clamped windows).
    auto mkinv = [&](int rh) -> float4 {
        auto f = [&](int gj) {
            const int nw = min(gj + rh, W_DIM - 1) - max(gj - rh, 0) + 1;
            return __frcp_rn((float)max(nw, 1));
        };
        return make_float4(f(gj0), f(gj0 + 1), f(gj0 + 2), f(gj0 + 3));
    };
    const float4 invnw1 = mkinv(2);
    const float4 invnw2 = mkinv(8);
    const bool storeOK = (lane >= LANELO) && (lane <= LANEHI) && colIn;

    // ---- Pass-1 producer state: vertical 17-row reload-sliding sum ----
    float4 vs1 = z4();
    #pragma unroll
    for (int k = 0; k < 16; k++)                 // rows (r0-2)-8 .. (r0-2)+7
        vs1 = add4(vs1, loadD1(r0 - 10 + k));

    // Produce X1 row r (updates vs1). Valid on lanes 1..30.
    auto stepX1 = [&](int r) -> float4 {
        const float4 nv1  = loadD1(r + 8);
        const float4 tot1 = add4(vs1, nv1);      // rows r-8 .. r+8
        const float4 hs1  = hsum_warp<2>(tot1);
        const int nh1 = min(r + 8, H_DIM - 1) - max(r - 8, 0) + 1;
        const float inv1 = __frcp_rn((float)max(nh1, 1));
        const float4 xr = load4p(X, r);
        float4 x1;
        x1.x = fmaf(hs1.x * inv1, invnw1.x, xr.x);
        x1.y = fmaf(hs1.y * inv1, invnw1.y, xr.y);
        x1.z = fmaf(hs1.z * inv1, invnw1.z, xr.z);
        x1.w = fmaf(hs1.w * inv1, invnw1.w, xr.w);
        const float4 ov1 = loadD1(r - 8);
        vs1 = sub4(tot1, ov1);
        return x1;
    };
    // D2 = Y - X1 at row r, zero outside the image.
    auto mkD2 = [&](int r, float4 x1) -> float4 {
        const bool rin = (unsigned)r < (unsigned)H_DIM;
        const float4 yr = load4p(Y, r);
        float4 d;
        d.x = (rin && c0) ? (yr.x - x1.x) : 0.f;
        d.y = (rin && c1) ? (yr.y - x1.y) : 0.f;
        d.z = (rin && c2) ? (yr.z - x1.z) : 0.f;
        d.w = (rin && c3) ? (yr.w - x1.w) : 0.f;
        return d;
    };

    // ---- Pass-2 state: 5-row D2 ring + 2-stage X1 shift register ----
    float4 ring2[4];
    float4 vs2 = z4();
    float4 x1m1 = z4(), x1m2 = z4();
    #pragma unroll
    for (int k = 0; k < 4; k++) {                // X1 / D2 rows r0-2 .. r0+1
        const int r = r0 - 2 + k;
        const float4 x1r = stepX1(r);
        const float4 d2  = mkD2(r, x1r);
        ring2[k] = d2;
        vs2 = add4(vs2, d2);
        x1m2 = x1m1; x1m1 = x1r;
    }
    // Now x1m2 = X1[r0], x1m1 = X1[r0+1].

    // ---- Main loop: one output row per iteration ----
    #pragma unroll 4
    for (int rr = 0; rr < SEG; rr++) {
        const int gi = r0 + rr;
        const int r  = gi + 2;
        const float4 x1r = stepX1(r);            // X1 row gi+2
        const float4 d2  = mkD2(r, x1r);
        const float4 tot2 = add4(vs2, d2);       // D2 rows gi-2 .. gi+2
        const float4 hs2  = hsum_warp<8>(tot2);
        const int nh2 = min(gi + 2, H_DIM - 1) - max(gi - 2, 0) + 1;
        const float inv2 = __frcp_rn((float)nh2);
        if (storeOK) {
            float4 o;
            o.x = fmaf(hs2.x * inv2, invnw2.x, x1m2.x);
            o.y = fmaf(hs2.y * inv2, invnw2.y, x1m2.y);
            o.z = fmaf(hs2.z * inv2, invnw2.z, x1m2.z);
            o.w = fmaf(hs2.w * inv2, invnw2.w, x1m2.w);
            *(float4*)(out + (size_t)gi * W_DIM + gj0) = o;
        }
        vs2 = sub4(tot2, ring2[rr & 3]);         // drop row gi-2
        ring2[rr & 3] = d2;
        x1m2 = x1m1; x1m1 = x1r;
    }
}

extern "C" void kernel_launch(void* const* d_in, const int* in_sizes, int n_in,
                              void* d_out, int out_size)
{
    const float* X = (const float*)d_in[0];
    const float* Y = (const float*)d_in[1];
    // d_in[2] is the (2,1,17,17) kernel tensor; fixed 17x5 / 5x17 boxes hard-coded.
    float* out = (float*)d_out;

    // 20 strips * 128 row-segments = 2560 warps = 320 blocks of 8 warps.
    guided_fused<<<320, 256>>>(X, Y, out);
}

// round 12
// speedup vs baseline: 1.1646x; 1.1646x over previous
#include <cuda_runtime.h>
#include <cuda_bf16.h>

// Fixed by the reference: 2048x2048 fp32, pass1 box = 17(v) x 5(h),
// pass2 box = 5(v) x 17(h); out = Xin + boxsum(y - Xin)/Ncount, zero-padded.
#define H_DIM 2048
#define W_DIM 2048

// 16 MB static scratch for the intermediate X1 (no allocations allowed).
__device__ float g_X1[H_DIM * W_DIM];

__device__ __forceinline__ float4 z4() { return make_float4(0.f, 0.f, 0.f, 0.f); }
__device__ __forceinline__ float4 ld4(const float* p) { return *(const float4*)p; }
__device__ __forceinline__ float4 add4(float4 a, float4 b) {
    return make_float4(a.x + b.x, a.y + b.y, a.z + b.z, a.w + b.w);
}
__device__ __forceinline__ float4 sub4(float4 a, float4 b) {
    return make_float4(a.x - b.x, a.y - b.y, a.z - b.z, a.w - b.w);
}

// Horizontal (2*RH+1)-tap box sum across the warp's 128 strip columns.
// Valid on lanes 1..30 (RH=2) / 2..29 (RH=8).
template <int RH>
__device__ __forceinline__ float4 hsum_warp(float4 t) {
    const unsigned M = 0xffffffffu;
    if constexpr (RH == 2) {
        const float Lz = __shfl_up_sync(M, t.z, 1);
        const float Lw = __shfl_up_sync(M, t.w, 1);
        const float Rx = __shfl_down_sync(M, t.x, 1);
        const float Ry = __shfl_down_sync(M, t.y, 1);
        const float sall = t.x + t.y + t.z + t.w;
        float4 hs;
        hs.y = Lw + sall;
        hs.x = hs.y + Lz - t.w;
        hs.z = sall + Rx;
        hs.w = hs.z - t.x + Ry;
        return hs;
    } else {  // RH == 8
        const float S    = t.x + t.y + t.z + t.w;
        const float Sm2  = __shfl_up_sync(M, S, 2);
        const float Sm1  = __shfl_up_sync(M, S, 1);
        const float Sp1  = __shfl_down_sync(M, S, 1);
        const float dxm2 = __shfl_up_sync(M, t.x, 2);
        const float dym2 = __shfl_up_sync(M, t.y, 2);
        const float dzm2 = __shfl_up_sync(M, t.z, 2);
        const float dxp2 = __shfl_down_sync(M, t.x, 2);
        const float dyp2 = __shfl_down_sync(M, t.y, 2);
        const float dzp2 = __shfl_down_sync(M, t.z, 2);
        const float dwp2 = __shfl_down_sync(M, t.w, 2);
        float4 hs;
        hs.x = Sm2 + Sm1 + S + Sp1 + dxp2;
        hs.y = hs.x - dxm2 + dyp2;
        hs.z = hs.y - dym2 + dzp2;
        hs.w = hs.z - dzm2 + dwp2;
        return hs;
    }
}

template <int RV, int RH, int SEG>
__global__ __launch_bounds__(256)
void guided_pass(const float* __restrict__ Xin,
                 const float* __restrict__ Y,
                 float* __restrict__ out)
{
    constexpr int OUTW   = (RH == 8) ? 112 : 120;  // output cols per warp strip
    constexpr int LANELO = (RH == 8) ? 2 : 1;
    constexpr int LANEHI = (RH == 8) ? 29 : 30;
    constexpr int STRIPS = (W_DIM + OUTW - 1) / OUTW;   // 19 / 18
    constexpr int SEGS   = H_DIM / SEG;
    constexpr int NTAPV  = 2 * RV + 1;

    const int wg    = blockIdx.x * 8 + (threadIdx.x >> 5);
    const int lane  = threadIdx.x & 31;
    const int strip = wg % STRIPS;
    const int segy  = wg / STRIPS;
    if (segy >= SEGS) return;

    const int r0  = segy * SEG;
    const int gj0 = strip * OUTW - 4 * LANELO + 4 * lane;  // 4-aligned
    const bool colIn = (gj0 >= 0) && (gj0 + 3 < W_DIM);
    const bool c0 = (unsigned)(gj0 + 0) < (unsigned)W_DIM;
    const bool c1 = (unsigned)(gj0 + 1) < (unsigned)W_DIM;
    const bool c2 = (unsigned)(gj0 + 2) < (unsigned)W_DIM;
    const bool c3 = (unsigned)(gj0 + 3) < (unsigned)W_DIM;

    // Predicated row load of one image (zeros outside image).
    auto load4p = [&](const float* base, int gi) -> float4 {
        if ((unsigned)gi >= (unsigned)H_DIM) return z4();
        const float* p = base + (size_t)gi * W_DIM + gj0;
        if (colIn) return ld4(p);
        float4 r = z4();
        if (c0) r.x = p[0];
        if (c1) r.y = p[1];
        if (c2) r.z = p[2];
        if (c3) r.w = p[3];
        return r;
    };
    // D = Y - Xin at row gi (zeros outside image).
    auto loadD = [&](int gi) -> float4 {
        if ((unsigned)gi >= (unsigned)H_DIM) return z4();
        const float* yp = Y   + (size_t)gi * W_DIM + gj0;
        const float* xp = Xin + (size_t)gi * W_DIM + gj0;
        if (colIn) return sub4(ld4(yp), ld4(xp));
        float4 r = z4();
        if (c0) r.x = yp[0] - xp[0];
        if (c1) r.y = yp[1] - xp[1];
        if (c2) r.z = yp[2] - xp[2];
        if (c3) r.w = yp[3] - xp[3];
        return r;
    };

    // Per-column 1/nw (clamped horizontal window count).
    float4 invnw;
    {
        auto f = [&](int gj) {
            const int nw = min(gj + RH, W_DIM - 1) - max(gj - RH, 0) + 1;
            return __frcp_rn((float)max(nw, 1));
        };
        invnw = make_float4(f(gj0), f(gj0 + 1), f(gj0 + 2), f(gj0 + 3));
    }
    const bool storeOK = (lane >= LANELO) && (lane <= LANEHI) && colIn;

    // Emit one output row given its vertical-sum total and the Xin row value.
    auto emit = [&](int gi, float4 tot, float4 xv) {
        const float4 hs = hsum_warp<RH>(tot);
        const int nh = min(gi + RV, H_DIM - 1) - max(gi - RV, 0) + 1;
        const float invnh = __frcp_rn((float)nh);
        if (storeOK) {
            float4 o;
            o.x = fmaf(hs.x * invnh, invnw.x, xv.x);
            o.y = fmaf(hs.y * invnh, invnw.y, xv.y);
            o.z = fmaf(hs.z * invnh, invnw.z, xv.z);
            o.w = fmaf(hs.w * invnh, invnw.w, xv.w);
            *(float4*)(out + (size_t)gi * W_DIM + gj0) = o;
        }
    };

    if constexpr (RV == 2) {
        // Ring-buffer vertical window (5 rows). Xin rows are kept in a 2-deep
        // shift register so the epilogue never reloads them.
        float4 ring[4];
        float4 vs = z4();
        float4 xa = z4(), xb = z4();       // Xin rows gi, gi+1 at emit time
        #pragma unroll
        for (int k = 0; k < 4; k++) {      // rows r0-2 .. r0+1
            const int r = r0 - 2 + k;
            const float4 xv = load4p(Xin, r);
            const float4 yv = load4p(Y, r);
            const float4 d  = sub4(yv, xv);
            ring[k] = d;
            vs = add4(vs, d);
            if (k == 2) xa = xv;           // Xin[r0]
            if (k == 3) xb = xv;           // Xin[r0+1]
        }
        #pragma unroll
        for (int rr = 0; rr < SEG; rr++) {
            const int gi = r0 + rr;
            const float4 xv = load4p(Xin, gi + 2);
            const float4 yv = load4p(Y, gi + 2);
            const float4 nv = sub4(yv, xv);
            const float4 tot = add4(vs, nv);      // rows gi-2 .. gi+2
            emit(gi, tot, xa);
            vs = sub4(tot, ring[rr & 3]);
            ring[rr & 3] = nv;
            xa = xb; xb = xv;
        }
    } else {
        // Reload-sliding vertical window (17 rows); old rows re-fetched
        // (L1/L2 hits — read 17 rows earlier by this warp).
        float4 vs = z4();
        #pragma unroll
        for (int k = 0; k < 2 * RV; k++)          // rows r0-8 .. r0+7
            vs = add4(vs, loadD(r0 - RV + k));
        #pragma unroll
        for (int rr = 0; rr < SEG; rr++) {
            const int gi = r0 + rr;
            const float4 nv  = loadD(gi + RV);
            const float4 tot = add4(vs, nv);      // rows gi-8 .. gi+8
            emit(gi, tot, load4p(Xin, gi));
            const float4 ov = loadD(gi - RV);
            vs = sub4(tot, ov);
        }
    }
    (void)NTAPV;
}

extern "C" void kernel_launch(void* const* d_in, const int* in_sizes, int n_in,
                              void* d_out, int out_size)
{
    const float* X = (const float*)d_in[0];
    const float* Y = (const float*)d_in[1];
    // d_in[2] is the (2,1,17,17) kernel tensor; fixed 17x5 / 5x17 boxes hard-coded.
    float* out = (float*)d_out;

    float* X1;
    cudaGetSymbolAddress((void**)&X1, g_X1);

    // Pass 1: RV=8, RH=2, SEG=8.  18 strips * 256 segs = 4608 warps = 576 blocks.
    guided_pass<8, 2, 8><<<576, 256>>>(X, Y, X1);
    // Pass 2: RV=2, RH=8, SEG=8.  19 strips * 256 segs = 4864 warps = 608 blocks.
    guided_pass<2, 8, 8><<<608, 256>>>(X1, Y, out);
}

// round 13
// speedup vs baseline: 1.1672x; 1.0022x over previous
#include <cuda_runtime.h>
#include <cuda_bf16.h>

// Fixed by the reference: 2048x2048 fp32, pass1 box = 17(v) x 5(h),
// pass2 box = 5(v) x 17(h); out = Xin + boxsum(y - Xin)/Ncount, zero-padded.
#define H_DIM 2048
#define W_DIM 2048

// 16 MB static scratch for the intermediate X1 (no allocations allowed).
__device__ float g_X1[H_DIM * W_DIM];

__device__ __forceinline__ float4 z4() { return make_float4(0.f, 0.f, 0.f, 0.f); }
__device__ __forceinline__ float4 ld4(const float* p) { return *(const float4*)p; }
__device__ __forceinline__ float4 add4(float4 a, float4 b) {
    return make_float4(a.x + b.x, a.y + b.y, a.z + b.z, a.w + b.w);
}
__device__ __forceinline__ float4 sub4(float4 a, float4 b) {
    return make_float4(a.x - b.x, a.y - b.y, a.z - b.z, a.w - b.w);
}

// Horizontal (2*RH+1)-tap box sum across the warp's 128 strip columns.
// Valid on lanes 1..30 (RH=2) / 2..29 (RH=8).
template <int RH>
__device__ __forceinline__ float4 hsum_warp(float4 t) {
    const unsigned M = 0xffffffffu;
    if constexpr (RH == 2) {
        const float Lz = __shfl_up_sync(M, t.z, 1);
        const float Lw = __shfl_up_sync(M, t.w, 1);
        const float Rx = __shfl_down_sync(M, t.x, 1);
        const float Ry = __shfl_down_sync(M, t.y, 1);
        const float sall = t.x + t.y + t.z + t.w;
        float4 hs;
        hs.y = Lw + sall;
        hs.x = hs.y + Lz - t.w;
        hs.z = sall + Rx;
        hs.w = hs.z - t.x + Ry;
        return hs;
    } else {  // RH == 8
        const float S    = t.x + t.y + t.z + t.w;
        const float Sm2  = __shfl_up_sync(M, S, 2);
        const float Sm1  = __shfl_up_sync(M, S, 1);
        const float Sp1  = __shfl_down_sync(M, S, 1);
        const float dxm2 = __shfl_up_sync(M, t.x, 2);
        const float dym2 = __shfl_up_sync(M, t.y, 2);
        const float dzm2 = __shfl_up_sync(M, t.z, 2);
        const float dxp2 = __shfl_down_sync(M, t.x, 2);
        const float dyp2 = __shfl_down_sync(M, t.y, 2);
        const float dzp2 = __shfl_down_sync(M, t.z, 2);
        const float dwp2 = __shfl_down_sync(M, t.w, 2);
        float4 hs;
        hs.x = Sm2 + Sm1 + S + Sp1 + dxp2;
        hs.y = hs.x - dxm2 + dyp2;
        hs.z = hs.y - dym2 + dzp2;
        hs.w = hs.z - dzm2 + dwp2;
        return hs;
    }
}

template <int RV, int RH, int SEG>
__global__ __launch_bounds__(256)
void guided_pass(const float* __restrict__ Xin,
                 const float* __restrict__ Y,
                 float* __restrict__ out)
{
    constexpr int OUTW   = (RH == 8) ? 112 : 120;  // output cols per warp strip
    constexpr int LANELO = (RH == 8) ? 2 : 1;
    constexpr int LANEHI = (RH == 8) ? 29 : 30;
    constexpr int STRIPS = (W_DIM + OUTW - 1) / OUTW;   // 19 / 18
    constexpr int SEGS   = H_DIM / SEG;

    const int wg    = blockIdx.x * 8 + (threadIdx.x >> 5);
    const int lane  = threadIdx.x & 31;
    const int strip = wg % STRIPS;
    const int segy  = wg / STRIPS;
    if (segy >= SEGS) return;

    const int r0  = segy * SEG;
    const int gj0 = strip * OUTW - 4 * LANELO + 4 * lane;  // 4-aligned
    const bool colIn = (gj0 >= 0) && (gj0 + 3 < W_DIM);
    const bool c0 = (unsigned)(gj0 + 0) < (unsigned)W_DIM;
    const bool c1 = (unsigned)(gj0 + 1) < (unsigned)W_DIM;
    const bool c2 = (unsigned)(gj0 + 2) < (unsigned)W_DIM;
    const bool c3 = (unsigned)(gj0 + 3) < (unsigned)W_DIM;

    // Predicated row load of one image (zeros outside image).
    auto load4p = [&](const float* base, int gi) -> float4 {
        if ((unsigned)gi >= (unsigned)H_DIM) return z4();
        const float* p = base + (size_t)gi * W_DIM + gj0;
        if (colIn) return ld4(p);
        float4 r = z4();
        if (c0) r.x = p[0];
        if (c1) r.y = p[1];
        if (c2) r.z = p[2];
        if (c3) r.w = p[3];
        return r;
    };
    // D = Y - Xin at row gi (zeros outside image).
    auto loadD = [&](int gi) -> float4 {
        if ((unsigned)gi >= (unsigned)H_DIM) return z4();
        const float* yp = Y   + (size_t)gi * W_DIM + gj0;
        const float* xp = Xin + (size_t)gi * W_DIM + gj0;
        if (colIn) return sub4(ld4(yp), ld4(xp));
        float4 r = z4();
        if (c0) r.x = yp[0] - xp[0];
        if (c1) r.y = yp[1] - xp[1];
        if (c2) r.z = yp[2] - xp[2];
        if (c3) r.w = yp[3] - xp[3];
        return r;
    };

    // Per-column 1/nw (clamped horizontal window count).
    float4 invnw;
    {
        auto f = [&](int gj) {
            const int nw = min(gj + RH, W_DIM - 1) - max(gj - RH, 0) + 1;
            return __frcp_rn((float)max(nw, 1));
        };
        invnw = make_float4(f(gj0), f(gj0 + 1), f(gj0 + 2), f(gj0 + 3));
    }
    const bool storeOK = (lane >= LANELO) && (lane <= LANEHI) && colIn;

    // Emit one output row from its vertical-sum float4. Xin row reloaded
    // here (L1 hit) — cheaper than carrying it in registers (R10 lesson).
    auto emit = [&](int gi, float4 tot) {
        const float4 hs = hsum_warp<RH>(tot);
        const int nh = min(gi + RV, H_DIM - 1) - max(gi - RV, 0) + 1;
        const float invnh = __frcp_rn((float)nh);
        if (storeOK) {
            const float4 xv = ld4(Xin + (size_t)gi * W_DIM + gj0);
            float4 o;
            o.x = fmaf(hs.x * invnh, invnw.x, xv.x);
            o.y = fmaf(hs.y * invnh, invnw.y, xv.y);
            o.z = fmaf(hs.z * invnh, invnw.z, xv.z);
            o.w = fmaf(hs.w * invnh, invnw.w, xv.w);
            *(float4*)(out + (size_t)gi * W_DIM + gj0) = o;
        }
    };

    if constexpr (RV == 2) {
        // Ring-buffer vertical sliding window (window 5).
        float4 ring[4];
        float4 vs = z4();
        #pragma unroll
        for (int k = 0; k < 4; k++) {          // rows r0-2 .. r0+1
            ring[k] = loadD(r0 - 2 + k);
            vs = add4(vs, ring[k]);
        }
        #pragma unroll
        for (int rr = 0; rr < SEG; rr++) {
            const int gi = r0 + rr;
            const float4 nv  = loadD(gi + 2);
            const float4 tot = add4(vs, nv);   // rows gi-2 .. gi+2
            emit(gi, tot);
            vs = sub4(tot, ring[rr & 3]);      // drop row gi-2
            ring[rr & 3] = nv;
        }
    } else {
        // Reload-sliding vertical window (17 rows); old rows re-fetched
        // (L1/L2 hits — read 17 rows earlier by this warp).
        float4 vs = z4();
        #pragma unroll
        for (int k = 0; k < 2 * RV; k++)       // rows r0-8 .. r0+7
            vs = add4(vs, loadD(r0 - RV + k));
        #pragma unroll
        for (int rr = 0; rr < SEG; rr++) {
            const int gi = r0 + rr;
            const float4 nv  = loadD(gi + RV);
            const float4 tot = add4(vs, nv);   // rows gi-8 .. gi+8
            emit(gi, tot);
            const float4 ov = loadD(gi - RV);
            vs = sub4(tot, ov);
        }
    }
}

extern "C" void kernel_launch(void* const* d_in, const int* in_sizes, int n_in,
                              void* d_out, int out_size)
{
    const float* X = (const float*)d_in[0];
    const float* Y = (const float*)d_in[1];
    // d_in[2] is the (2,1,17,17) kernel tensor; fixed 17x5 / 5x17 boxes hard-coded.
    float* out = (float*)d_out;

    float* X1;
    cudaGetSymbolAddress((void**)&X1, g_X1);

    // Pass 1: RV=8, RH=2, SEG=8.  18 strips * 256 segs = 4608 warps = 576 blocks.
    guided_pass<8, 2, 8><<<576, 256>>>(X, Y, X1);
    // Pass 2: RV=2, RH=8, SEG=4.  19 strips * 512 segs = 9728 warps = 1216 blocks.
    guided_pass<2, 8, 4><<<1216, 256>>>(X1, Y, out);
}